// round 13
// baseline (speedup 1.0000x reference)
#include <cuda_runtime.h>
#include <cuda_bf16.h>
#include <math.h>
#include <stdint.h>

// Problem constants
#define B_  2
#define S_  2048
#define D_  1024
#define H_  16
#define HD_ 64
#define MS_ (B_ * S_)        // 4096 rows
#define NQKV_ (3 * D_)       // 3072

// ---------------------------------------------------------------------------
// Device-global scratch
// ---------------------------------------------------------------------------
__device__ float g_qkv[(size_t)MS_ * NQKV_];   // QKV projection output (fp32)

// bf16 splits, ALL in perm8 u32-pair layout
__device__ __nv_bfloat16 g_xh[(size_t)MS_ * D_],  g_xl[(size_t)MS_ * D_];
__device__ __nv_bfloat16 g_wh[(size_t)NQKV_ * D_], g_wl[(size_t)NQKV_ * D_]; // qkv_w^T
__device__ __nv_bfloat16 g_oh[(size_t)D_ * D_],   g_ol[(size_t)D_ * D_];     // out_w^T
__device__ __nv_bfloat16 g_ah[(size_t)MS_ * D_],  g_al[(size_t)MS_ * D_];    // att split

// flash operands: q/k: [b,h,s,d] (32 u32/row), v: [b,h,d,s-pairs]
#define FQK_ELEMS ((size_t)B_ * H_ * S_ * HD_)
__device__ __nv_bfloat16 g_fqh[FQK_ELEMS], g_fql[FQK_ELEMS];
__device__ __nv_bfloat16 g_fkh[FQK_ELEMS], g_fkl[FQK_ELEMS];
__device__ __nv_bfloat16 g_fvh[FQK_ELEMS], g_fvl[FQK_ELEMS];

// ---------------------------------------------------------------------------
// Base-ISA helpers (no tcgen05/TMA: harness compiles for compute_103 base)
// ---------------------------------------------------------------------------
#define CP_ASYNC16(dst_u32, src_ptr) \
    asm volatile("cp.async.cg.shared.global [%0], [%1], 16;" \
                 :: "r"(dst_u32), "l"(src_ptr) : "memory")
#define CP_COMMIT() asm volatile("cp.async.commit_group;" ::: "memory")
#define CP_WAIT(n)  asm volatile("cp.async.wait_group %0;" :: "n"(n) : "memory")

__device__ __forceinline__ uint32_t smem_u32(const void* p) {
    uint32_t a;
    asm("{ .reg .u64 t; cvta.to.shared.u64 t, %1; cvt.u32.u64 %0, t; }"
        : "=r"(a) : "l"(p));
    return a;
}

__device__ __forceinline__ void mma_bf16(float* c, const uint32_t* a,
                                         const uint32_t* b) {
    asm volatile(
        "mma.sync.aligned.m16n8k16.row.col.f32.bf16.bf16.f32 "
        "{%0,%1,%2,%3}, {%4,%5,%6,%7}, {%8,%9}, {%0,%1,%2,%3};"
        : "+f"(c[0]), "+f"(c[1]), "+f"(c[2]), "+f"(c[3])
        : "r"(a[0]), "r"(a[1]), "r"(a[2]), "r"(a[3]), "r"(b[0]), "r"(b[1]));
}

__device__ __forceinline__ void psplit(float vlo, float vhi,
                                       uint32_t& hp, uint32_t& lp) {
    asm("cvt.rn.bf16x2.f32 %0, %1, %2;" : "=r"(hp) : "f"(vhi), "f"(vlo));
    float hlo = __int_as_float(hp << 16);
    float hhi = __int_as_float(hp & 0xFFFF0000u);
    float llo = vlo - hlo, lhi = vhi - hhi;
    asm("cvt.rn.bf16x2.f32 %0, %1, %2;" : "=r"(lp) : "f"(lhi), "f"(llo));
}

// fast 2^x, FMA/ALU pipes only
__device__ __forceinline__ float fexp2(float x) {
    x = fmaxf(x, -126.0f);
    float fi = x + 12582912.0f;
    int   i  = __float_as_int(fi) - 0x4B400000;
    float f  = x - (fi - 12582912.0f);
    float p  = 0.00133336f;
    p = fmaf(p, f, 0.00961813f);
    p = fmaf(p, f, 0.05550411f);
    p = fmaf(p, f, 0.24022651f);
    p = fmaf(p, f, 0.69314718f);
    p = fmaf(p, f, 1.0f);
    return p * __int_as_float((i + 127) << 23);
}

__device__ __forceinline__ int perm8(int o) { return (o < 4) ? 2 * o : 2 * (o - 4) + 1; }

// ---------------------------------------------------------------------------
// Split kernels -> perm8 layout (unchanged, passing)
// ---------------------------------------------------------------------------
__global__ void __launch_bounds__(256) split_kernel_p(
    const float4* __restrict__ src, uint32_t* __restrict__ hi,
    uint32_t* __restrict__ lo, int n4)
{
    int i = blockIdx.x * 256 + threadIdx.x;
    if (i >= n4) return;
    float4 v = src[i];
    uint32_t h0, l0, h1, l1;
    psplit(v.x, v.y, h0, l0);
    psplit(v.z, v.w, h1, l1);
    int u0 = 2 * i;
    int base = u0 & ~7;
    int d0 = base + perm8(u0 & 7);
    int d1 = base + perm8((u0 + 1) & 7);
    hi[d0] = h0;  hi[d1] = h1;
    lo[d0] = l0;  lo[d1] = l1;
}

__global__ void __launch_bounds__(256) split_transpose_p(
    const float* __restrict__ src, __nv_bfloat16* __restrict__ hi,
    __nv_bfloat16* __restrict__ lo, int R, int C)
{
    __shared__ float t[32][33];
    int c0 = blockIdx.x * 32, r0 = blockIdx.y * 32;
    int tx = threadIdx.x, ty = threadIdx.y;
    #pragma unroll
    for (int i = 0; i < 4; i++) {
        int r = r0 + ty + i * 8;
        t[ty + i * 8][tx] = src[(size_t)r * C + c0 + tx];
    }
    __syncthreads();
    #pragma unroll
    for (int i = 0; i < 4; i++) {
        int n = c0 + ty + i * 8;
        float v = t[tx][ty + i * 8];
        __nv_bfloat16 h = __float2bfloat16(v);
        int e = r0 + tx;
        int ep = (e & ~15) + perm8((e >> 1) & 7) * 2 + (e & 1);
        hi[(size_t)n * R + ep] = h;
        lo[(size_t)n * R + ep] = __float2bfloat16(v - __bfloat162float(h));
    }
}

// ---------------------------------------------------------------------------
// HMMA bf16-split GEMM v3: all smem addresses precomputed (4 regs),
// 3-stage cp.async, one barrier per K-block, lds.64 fragments. 2 CTAs/SM.
// ---------------------------------------------------------------------------
#define GEMM_SMEM (3 * 32768)

__device__ __forceinline__ int gfrag(int r, int ks, int tig) {
    return r * 16 + (((2 * ks + (tig >> 1) + (r & 2)) & 3) << 2) + ((tig & 1) << 1);
}

__global__ void __launch_bounds__(256, 2)
gemm_mma_kernel(const __nv_bfloat16* __restrict__ Ah,
                const __nv_bfloat16* __restrict__ Al,
                const __nv_bfloat16* __restrict__ Bth,
                const __nv_bfloat16* __restrict__ Btl,
                const float* __restrict__ bias, float* __restrict__ C,
                int M, int N, int K)
{
    extern __shared__ uint32_t fsm[];
    const uint32_t sb = smem_u32(fsm);
    const int tid  = threadIdx.x;
    const int wid  = tid >> 5;
    const int lane = tid & 31;
    const int gid  = lane >> 2;
    const int tig  = lane & 3;
    const int wm   = (wid & 3) * 32;
    const int wn   = (wid >> 2) * 64;

    const int brow = blockIdx.y * 128;
    const int bcol = blockIdx.x * 128;
    const size_t rowb = (size_t)K * 2;

    // ---- precomputed cp.async addressing (loop-invariant) ----
    const int grow0 = tid >> 2, gch0 = tid & 3;
    const uint32_t dstoff0 = (uint32_t)(grow0 * 64 + (((gch0 + (grow0 & 2)) & 3) << 4));
    const size_t soff0 = (size_t)grow0 * rowb + gch0 * 16;
    const size_t soff1 = soff0 + 64 * rowb;
    const char* b0 = (const char*)(Ah  + (size_t)brow * K) + soff0;
    const char* b1 = (const char*)(Al  + (size_t)brow * K) + soff0;
    const char* b2 = (const char*)(Bth + (size_t)bcol * K) + soff0;
    const char* b3 = (const char*)(Btl + (size_t)bcol * K) + soff0;
    const size_t d1 = soff1 - soff0;

    auto issue = [&](int slot, int kb) {
        const uint32_t stg = sb + (uint32_t)slot * 32768u + dstoff0;
        const size_t ko = (size_t)kb * 64;
        CP_ASYNC16(stg,                 b0 + ko);
        CP_ASYNC16(stg + 4096u,         b0 + ko + d1);
        CP_ASYNC16(stg + 8192u,         b1 + ko);
        CP_ASYNC16(stg + 8192u + 4096u, b1 + ko + d1);
        CP_ASYNC16(stg + 16384u,          b2 + ko);
        CP_ASYNC16(stg + 16384u + 4096u,  b2 + ko + d1);
        CP_ASYNC16(stg + 24576u,          b3 + ko);
        CP_ASYNC16(stg + 24576u + 4096u,  b3 + ko + d1);
    };

    // ---- precomputed fragment offsets (4 regs; +8/+16 rows are +128/+256) ----
    const int aoff0 = gfrag(wm + gid, 0, tig), aoff1 = gfrag(wm + gid, 1, tig);
    const int boff0 = gfrag(wn + gid, 0, tig), boff1 = gfrag(wn + gid, 1, tig);

    const int NKB = K >> 5;
    issue(0, 0); CP_COMMIT();
    issue(1, 1); CP_COMMIT();

    float acc[2][8][4];
    #pragma unroll
    for (int mt = 0; mt < 2; mt++)
        #pragma unroll
        for (int nt = 0; nt < 8; nt++)
            #pragma unroll
            for (int e = 0; e < 4; e++) acc[mt][nt][e] = 0.0f;

    int cstage = 0, istage = 2;
    for (int kb = 0; kb < NKB; kb++) {
        if (kb + 1 < NKB) { CP_WAIT(1); } else { CP_WAIT(0); }
        __syncthreads();
        if (kb + 2 < NKB) {
            issue(istage, kb + 2); CP_COMMIT();
            istage = (istage == 2) ? 0 : istage + 1;
        }

        const uint32_t* st = fsm + cstage * 8192;
        cstage = (cstage == 2) ? 0 : cstage + 1;

        #pragma unroll
        for (int ks = 0; ks < 2; ks++) {
            const uint32_t* Ap = st + (ks ? aoff1 : aoff0);
            const uint32_t* Bp = st + 4096 + (ks ? boff1 : boff0);
            uint32_t ah[2][4], al[2][4];
            #pragma unroll
            for (int mt = 0; mt < 2; mt++) {
                uint2 h0 = *(const uint2*)(Ap + mt * 256);
                uint2 h1 = *(const uint2*)(Ap + mt * 256 + 128);
                uint2 l0 = *(const uint2*)(Ap + 2048 + mt * 256);
                uint2 l1 = *(const uint2*)(Ap + 2048 + mt * 256 + 128);
                ah[mt][0] = h0.x; ah[mt][1] = h1.x; ah[mt][2] = h0.y; ah[mt][3] = h1.y;
                al[mt][0] = l0.x; al[mt][1] = l1.x; al[mt][2] = l0.y; al[mt][3] = l1.y;
            }
            #pragma unroll
            for (int nt = 0; nt < 8; nt++) {
                uint2 bh2 = *(const uint2*)(Bp + nt * 128);
                uint2 bl2 = *(const uint2*)(Bp + 2048 + nt * 128);
                uint32_t bh[2] = {bh2.x, bh2.y};
                uint32_t bl[2] = {bl2.x, bl2.y};
                #pragma unroll
                for (int mt = 0; mt < 2; mt++) {
                    mma_bf16(acc[mt][nt], ah[mt], bh);
                    mma_bf16(acc[mt][nt], ah[mt], bl);
                    mma_bf16(acc[mt][nt], al[mt], bh);
                }
            }
        }
    }

    #pragma unroll
    for (int mt = 0; mt < 2; mt++) {
        const int gr = brow + wm + mt * 16 + gid;
        #pragma unroll
        for (int nt = 0; nt < 8; nt++) {
            const int gc = bcol + wn + nt * 8 + tig * 2;
            const float2 bb = *(const float2*)(bias + gc);
            float2 o0, o1;
            o0.x = acc[mt][nt][0] + bb.x;  o0.y = acc[mt][nt][1] + bb.y;
            o1.x = acc[mt][nt][2] + bb.x;  o1.y = acc[mt][nt][3] + bb.y;
            *(float2*)(C + (size_t)gr * N + gc)       = o0;
            *(float2*)(C + (size_t)(gr + 8) * N + gc) = o1;
        }
    }
}

// ---------------------------------------------------------------------------
// Prep kernels (unchanged, passing)
// ---------------------------------------------------------------------------
__global__ void __launch_bounds__(256) prep_qk_kernel()
{
    int t = blockIdx.x * 256 + threadIdx.x;
    int d2 = t & 31;
    int s  = (t >> 5) & (S_ - 1);
    int bh = t >> 16;
    int h = bh & (H_ - 1), b = bh >> 4;
    size_t row = ((size_t)(b * S_ + s)) * NQKV_ + h * HD_ + 2 * d2;
    float2 q = *(const float2*)(g_qkv + row);
    float2 k = *(const float2*)(g_qkv + row + D_);
    int outc = (d2 & ~7) | perm8(d2 & 7);
    size_t oidx = ((size_t)bh * S_ + s) * 32 + outc;
    const float Cc = 0.18033688f;                // 0.125 * log2(e)
    q.x *= Cc; q.y *= Cc;
    uint32_t qh, ql, kh, kl;
    psplit(q.x, q.y, qh, ql);
    psplit(k.x, k.y, kh, kl);
    ((uint32_t*)g_fqh)[oidx] = qh;  ((uint32_t*)g_fql)[oidx] = ql;
    ((uint32_t*)g_fkh)[oidx] = kh;  ((uint32_t*)g_fkl)[oidx] = kl;
}

__global__ void __launch_bounds__(256) prep_v_kernel()
{
    __shared__ float tile[64][65];
    int s0 = blockIdx.x * 64, h = blockIdx.y, b = blockIdx.z;
    int tid = threadIdx.x;
    for (int i = tid; i < 64 * 64; i += 256) {
        int r = i >> 6, d = i & 63;
        tile[r][d] = g_qkv[((size_t)(b * S_ + s0 + r)) * NQKV_ + 2 * D_ + h * HD_ + d];
    }
    __syncthreads();
    int bh = b * H_ + h;
    for (int i = tid; i < 64 * 32; i += 256) {
        int d = i >> 5, s2 = i & 31;
        float v0 = tile[2 * s2][d], v1 = tile[2 * s2 + 1][d];
        uint32_t vh, vl;
        psplit(v0, v1, vh, vl);
        int sp = (s0 >> 1) + s2;
        int outc = (sp & ~7) | perm8(sp & 7);
        size_t oidx = ((size_t)bh * HD_ + d) * (S_ / 2) + outc;
        ((uint32_t*)g_fvh)[oidx] = vh;
        ((uint32_t*)g_fvl)[oidx] = vl;
    }
}

// ---------------------------------------------------------------------------
// Flash attention v3: 3-stage 96KB pipeline, no reg cap (no spills),
// precomputed fragment/copy offsets. Epilogue writes perm8 split for GEMM2.
// ---------------------------------------------------------------------------
#define FLASH_SMEM (3 * 32768)

__device__ __forceinline__ int ffrag(int r, int kk, int tig) {
    return r * 32 + (((2 * kk + (tig >> 1) + 2 * r) & 7) << 2) + ((tig & 1) << 1);
}

__global__ void __launch_bounds__(256) flash_mma_kernel()
{
    extern __shared__ uint32_t fsm[];
    const uint32_t sb = smem_u32(fsm);
    const int tid = threadIdx.x, wid = tid >> 5, lane = tid & 31;
    const int gid = lane >> 2, tig = lane & 3;
    const int qt = gridDim.x - 1 - blockIdx.x;   // longest CTAs first
    const int h = blockIdx.y, b = blockIdx.z;
    const int bh = b * H_ + h;

    // ---- precomputed copy addressing ----
    const int crow = tid >> 3, cch = tid & 7;
    const uint32_t dstoff0 = (uint32_t)(crow * 128 + (((cch + 2 * crow) & 7) << 4));
    const uint32_t dstoff1 = (uint32_t)((crow + 32) * 128 + (((cch + 2 * (crow + 32)) & 7) << 4));
    const size_t sk0 = (size_t)crow * 128 + cch * 16;
    const size_t sk1 = sk0 + 32 * 128;
    const size_t sv0 = (size_t)crow * 4096 + cch * 16;
    const size_t sv1 = sv0 + 32 * 4096;
    const char* khb = (const char*)g_fkh + ((size_t)bh * S_) * 128;
    const char* klb = (const char*)g_fkl + ((size_t)bh * S_) * 128;
    const char* vhb = (const char*)g_fvh + ((size_t)bh * HD_) * 4096;
    const char* vlb = (const char*)g_fvl + ((size_t)bh * HD_) * 4096;

    auto issue = [&](int slot, int kt) {
        const uint32_t stg = sb + (uint32_t)slot * 32768u;
        const size_t kk = (size_t)kt * 8192;   // 64 keys * 128B
        const size_t vv = (size_t)kt * 128;    // 32 pair-cols * 4B... (bytes)
        CP_ASYNC16(stg + dstoff0,          khb + kk + sk0);
        CP_ASYNC16(stg + dstoff1,          khb + kk + sk1);
        CP_ASYNC16(stg + 8192u + dstoff0,  klb + kk + sk0);
        CP_ASYNC16(stg + 8192u + dstoff1,  klb + kk + sk1);
        CP_ASYNC16(stg + 16384u + dstoff0, vhb + vv + sv0);
        CP_ASYNC16(stg + 16384u + dstoff1, vhb + vv + sv1);
        CP_ASYNC16(stg + 24576u + dstoff0, vlb + vv + sv0);
        CP_ASYNC16(stg + 24576u + dstoff1, vlb + vv + sv1);
    };

    // ---- precomputed fragment offsets (shared by K and V reads) ----
    int koff[4];
    #pragma unroll
    for (int kk = 0; kk < 4; kk++) koff[kk] = ffrag(gid, kk, tig);

    // Q fragments via LDG (one-time)
    uint32_t qfh[4][4], qfl[4][4];
    {
        const uint2* qhp = (const uint2*)g_fqh;
        const uint2* qlp = (const uint2*)g_fql;
        size_t rb = ((size_t)bh * S_ + (size_t)qt * 128 + wid * 16 + gid) * 16;
        #pragma unroll
        for (int kk = 0; kk < 4; kk++) {
            uint2 h0 = qhp[rb + kk * 4 + tig];
            uint2 h1 = qhp[rb + 128 + kk * 4 + tig];
            qfh[kk][0] = h0.x; qfh[kk][1] = h1.x; qfh[kk][2] = h0.y; qfh[kk][3] = h1.y;
            uint2 l0 = qlp[rb + kk * 4 + tig];
            uint2 l1 = qlp[rb + 128 + kk * 4 + tig];
            qfl[kk][0] = l0.x; qfl[kk][1] = l1.x; qfl[kk][2] = l0.y; qfl[kk][3] = l1.y;
        }
    }

    const int KT = 2 * qt + 2;
    issue(0, 0); CP_COMMIT();
    if (KT > 1) { issue(1, 1); CP_COMMIT(); }

    float o[8][4];
    #pragma unroll
    for (int fo = 0; fo < 8; fo++)
        #pragma unroll
        for (int e = 0; e < 4; e++) o[fo][e] = 0.0f;
    float m0 = -INFINITY, m1 = -INFINITY, l0 = 0.0f, l1 = 0.0f;

    const int q0 = qt * 128 + 16 * wid + gid;
    const int q1 = q0 + 8;
    const int qmax = qt * 128 + 16 * wid + 15;

    int cstage = 0, istage = (KT > 1) ? 2 : 1;
    for (int kt = 0; kt < KT; kt++) {
        if (kt + 1 < KT) { CP_WAIT(1); } else { CP_WAIT(0); }
        __syncthreads();
        if (kt + 2 < KT) {
            issue(istage, kt + 2); CP_COMMIT();
            istage = (istage == 2) ? 0 : istage + 1;
        }

        const uint32_t* KH = fsm + cstage * 8192;
        const uint32_t* KL = KH + 2048;
        const uint32_t* VH = KH + 4096;
        const uint32_t* VL = KH + 6144;
        cstage = (cstage == 2) ? 0 : cstage + 1;
        const bool diag = ((kt >> 1) == qt);

        // S = Q K^T (3-MMA split)
        float s[8][4];
        #pragma unroll
        for (int f = 0; f < 8; f++) {
            const int key0 = kt * 64 + 8 * f;
            if (diag && key0 > qmax) {
                s[f][0] = s[f][1] = s[f][2] = s[f][3] = -1e30f;
                continue;
            }
            float c4[4] = {0.0f, 0.0f, 0.0f, 0.0f};
            #pragma unroll
            for (int kk = 0; kk < 4; kk++) {
                uint2 bh2 = *(const uint2*)(KH + koff[kk] + f * 256);
                uint2 bl2 = *(const uint2*)(KL + koff[kk] + f * 256);
                uint32_t bhf[2] = {bh2.x, bh2.y};
                uint32_t blf[2] = {bl2.x, bl2.y};
                mma_bf16(c4, qfh[kk], bhf);
                mma_bf16(c4, qfh[kk], blf);
                mma_bf16(c4, qfl[kk], bhf);
            }
            if (diag) {
                int key = key0 + 2 * tig;
                if (key     > q0) c4[0] = -1e30f;
                if (key + 1 > q0) c4[1] = -1e30f;
                if (key     > q1) c4[2] = -1e30f;
                if (key + 1 > q1) c4[3] = -1e30f;
            }
            s[f][0] = c4[0]; s[f][1] = c4[1]; s[f][2] = c4[2]; s[f][3] = c4[3];
        }

        // streaming softmax (log2 domain)
        float rm0 = -1e30f, rm1 = -1e30f;
        #pragma unroll
        for (int f = 0; f < 8; f++) {
            rm0 = fmaxf(rm0, fmaxf(s[f][0], s[f][1]));
            rm1 = fmaxf(rm1, fmaxf(s[f][2], s[f][3]));
        }
        rm0 = fmaxf(rm0, __shfl_xor_sync(0xffffffffu, rm0, 1));
        rm0 = fmaxf(rm0, __shfl_xor_sync(0xffffffffu, rm0, 2));
        rm1 = fmaxf(rm1, __shfl_xor_sync(0xffffffffu, rm1, 1));
        rm1 = fmaxf(rm1, __shfl_xor_sync(0xffffffffu, rm1, 2));
        float mn0 = fmaxf(m0, rm0), mn1 = fmaxf(m1, rm1);
        float corr0 = fexp2(m0 - mn0), corr1 = fexp2(m1 - mn1);
        float rs0 = 0.0f, rs1 = 0.0f;
        #pragma unroll
        for (int f = 0; f < 8; f++) {
            s[f][0] = fexp2(s[f][0] - mn0);
            s[f][1] = fexp2(s[f][1] - mn0);
            s[f][2] = fexp2(s[f][2] - mn1);
            s[f][3] = fexp2(s[f][3] - mn1);
            rs0 += s[f][0] + s[f][1];
            rs1 += s[f][2] + s[f][3];
        }
        rs0 += __shfl_xor_sync(0xffffffffu, rs0, 1);
        rs0 += __shfl_xor_sync(0xffffffffu, rs0, 2);
        rs1 += __shfl_xor_sync(0xffffffffu, rs1, 1);
        rs1 += __shfl_xor_sync(0xffffffffu, rs1, 2);
        l0 = l0 * corr0 + rs0;  m0 = mn0;
        l1 = l1 * corr1 + rs1;  m1 = mn1;
        #pragma unroll
        for (int fo = 0; fo < 8; fo++) {
            o[fo][0] *= corr0;  o[fo][1] *= corr0;
            o[fo][2] *= corr1;  o[fo][3] *= corr1;
        }

        // P -> bf16 hi/lo A-fragments
        uint32_t ph[4][4], pl[4][4];
        #pragma unroll
        for (int j = 0; j < 4; j++) {
            if (diag && (kt * 64 + 16 * j > qmax)) continue;
            psplit(s[2 * j][0],     s[2 * j][1],     ph[j][0], pl[j][0]);
            psplit(s[2 * j][2],     s[2 * j][3],     ph[j][1], pl[j][1]);
            psplit(s[2 * j + 1][0], s[2 * j + 1][1], ph[j][2], pl[j][2]);
            psplit(s[2 * j + 1][2], s[2 * j + 1][3], ph[j][3], pl[j][3]);
        }

        // O += P V (3-MMA split)
        #pragma unroll
        for (int j = 0; j < 4; j++) {
            if (diag && (kt * 64 + 16 * j > qmax)) continue;
            #pragma unroll
            for (int fo = 0; fo < 8; fo++) {
                uint2 vh2 = *(const uint2*)(VH + koff[j] + fo * 256);
                uint2 vl2 = *(const uint2*)(VL + koff[j] + fo * 256);
                uint32_t bhf[2] = {vh2.x, vh2.y};
                uint32_t blf[2] = {vl2.x, vl2.y};
                mma_bf16(o[fo], ph[j], bhf);
                mma_bf16(o[fo], pl[j], bhf);
                mma_bf16(o[fo], ph[j], blf);
            }
        }
    }

    // normalize + write bf16 hi/lo split directly (perm8 GEMM-A layout)
    float inv0 = 1.0f / l0, inv1 = 1.0f / l1;
    uint32_t* AH = (uint32_t*)g_ah;
    uint32_t* AL = (uint32_t*)g_al;
    const size_t row0 = ((size_t)(b * S_) + q0) * 512;
    const size_t row1 = ((size_t)(b * S_) + q1) * 512;
    #pragma unroll
    for (int fo = 0; fo < 8; fo++) {
        int ucol = 4 * fo + tig;
        int pos = h * 32 + (ucol & ~7) + perm8(ucol & 7);
        uint32_t hp, lp;
        psplit(o[fo][0] * inv0, o[fo][1] * inv0, hp, lp);
        AH[row0 + pos] = hp;  AL[row0 + pos] = lp;
        psplit(o[fo][2] * inv1, o[fo][3] * inv1, hp, lp);
        AH[row1 + pos] = hp;  AL[row1 + pos] = lp;
    }
}

// ---------------------------------------------------------------------------
// kernel_launch
// ---------------------------------------------------------------------------
extern "C" void kernel_launch(void* const* d_in, const int* in_sizes, int n_in,
                              void* d_out, int out_size)
{
    const float* x     = (const float*)d_in[0];
    const float* qkv_w = (const float*)d_in[1];
    const float* qkv_b = (const float*)d_in[2];
    const float* out_w = (const float*)d_in[3];
    const float* out_b = (const float*)d_in[4];
    float* out = (float*)d_out;

    float *qkv_buf;
    __nv_bfloat16 *xh, *xl, *wh, *wl, *oh, *ol, *ah, *al;
    cudaGetSymbolAddress((void**)&qkv_buf, g_qkv);
    cudaGetSymbolAddress((void**)&xh, g_xh);
    cudaGetSymbolAddress((void**)&xl, g_xl);
    cudaGetSymbolAddress((void**)&wh, g_wh);
    cudaGetSymbolAddress((void**)&wl, g_wl);
    cudaGetSymbolAddress((void**)&oh, g_oh);
    cudaGetSymbolAddress((void**)&ol, g_ol);
    cudaGetSymbolAddress((void**)&ah, g_ah);
    cudaGetSymbolAddress((void**)&al, g_al);

    cudaFuncSetAttribute(gemm_mma_kernel,
                         cudaFuncAttributeMaxDynamicSharedMemorySize, GEMM_SMEM);
    cudaFuncSetAttribute(flash_mma_kernel,
                         cudaFuncAttributeMaxDynamicSharedMemorySize, FLASH_SMEM);

    // Split inputs (perm8 layout)
    {
        int n4 = MS_ * D_ / 4;
        split_kernel_p<<<(n4 + 255) / 256, 256>>>(
            (const float4*)x, (uint32_t*)xh, (uint32_t*)xl, n4);
    }
    split_transpose_p<<<dim3(NQKV_ / 32, D_ / 32), dim3(32, 8)>>>(
        qkv_w, wh, wl, D_, NQKV_);
    split_transpose_p<<<dim3(D_ / 32, D_ / 32), dim3(32, 8)>>>(
        out_w, oh, ol, D_, D_);

    // 1) QKV projection
    gemm_mma_kernel<<<dim3(NQKV_ / 128, MS_ / 128), 256, GEMM_SMEM>>>(
        xh, xl, wh, wl, qkv_b, qkv_buf, MS_, NQKV_, D_);

    // 2) prep flash operands, then flash attention (writes g_ah/g_al)
    prep_qk_kernel<<<(B_ * H_ * S_ * 32) / 256, 256>>>();
    prep_v_kernel<<<dim3(S_ / 64, H_, B_), 256>>>();
    flash_mma_kernel<<<dim3(S_ / 128, H_, B_), 256, FLASH_SMEM>>>();

    // 3) output projection
    gemm_mma_kernel<<<dim3(D_ / 128, MS_ / 128), 256, GEMM_SMEM>>>(
        ah, al, oh, ol, out_b, out, MS_, D_, D_);
}